// round 15
// baseline (speedup 1.0000x reference)
#include <cuda_runtime.h>
#include <cuda_fp16.h>
#include <cstdint>

#define BATCH    2
#define SEQ      2048
#define DMODEL   1024
#define NHEADS   16
#define HEADDIM  64
#define MROWS    (BATCH * SEQ)
#define BH       (BATCH * NHEADS)

__device__ __half g_in[3][MROWS * DMODEL];    // fp16 inputs
__device__ __half g_w[4][DMODEL * DMODEL];    // fp16 weights
__device__ __half g_qh[BH * SEQ * HEADDIM];   // [bh][s][dh], pre-scaled by log2e/8
__device__ __half g_kh[BH * SEQ * HEADDIM];
__device__ __half g_vh[BH * SEQ * HEADDIM];
__device__ __half g_ctx[MROWS * DMODEL];

__device__ __forceinline__ uint32_t smem_u32(const void* p) {
    uint32_t a;
    asm("{ .reg .u64 t; cvta.to.shared.u64 t, %1; cvt.u32.u64 %0, t; }" : "=r"(a) : "l"(p));
    return a;
}
#define CP16(sp, gp)  asm volatile("cp.async.cg.shared.global [%0], [%1], 16;" :: "r"(sp), "l"(gp))
#define CP_COMMIT()   asm volatile("cp.async.commit_group;" ::: "memory")
#define CP_WAIT1()    asm volatile("cp.async.wait_group 1;" ::: "memory")
#define CP_WAIT2()    asm volatile("cp.async.wait_group 2;" ::: "memory")
#define LDSM4(r0, r1, r2, r3, addr) \
    asm volatile("ldmatrix.sync.aligned.m8n8.x4.shared.b16 {%0,%1,%2,%3}, [%4];" \
                 : "=r"(r0), "=r"(r1), "=r"(r2), "=r"(r3) : "r"(addr))
#define LDSMT4(r0, r1, r2, r3, addr) \
    asm volatile("ldmatrix.sync.aligned.m8n8.x4.trans.shared.b16 {%0,%1,%2,%3}, [%4];" \
                 : "=r"(r0), "=r"(r1), "=r"(r2), "=r"(r3) : "r"(addr))
#define MMAF16(c, a, b) \
    asm volatile("mma.sync.aligned.m16n8k16.row.col.f32.f16.f16.f32 " \
                 "{%0,%1,%2,%3}, {%4,%5,%6,%7}, {%8,%9}, {%0,%1,%2,%3};" \
                 : "+f"((c)[0]), "+f"((c)[1]), "+f"((c)[2]), "+f"((c)[3]) \
                 : "r"((a)[0]), "r"((a)[1]), "r"((a)[2]), "r"((a)[3]), \
                   "r"((b)[0]), "r"((b)[1]))
#define EX2(d, x) asm("ex2.approx.f32 %0, %1;" : "=f"(d) : "f"(x))

__device__ __forceinline__ uint32_t f22h(float a, float b) {
    __half2 h = __floats2half2_rn(a, b);
    return *reinterpret_cast<uint32_t*>(&h);
}

// One launch converts all 7 fp32 tensors to fp16. blockIdx.y selects tensor.
__global__ void convert_kernel(const float* __restrict__ Q, const float* __restrict__ K,
                               const float* __restrict__ V, const float* __restrict__ Wq,
                               const float* __restrict__ Wk, const float* __restrict__ Wv,
                               const float* __restrict__ Wo)
{
    const int which = blockIdx.y;
    const float* src;
    __half* dst;
    int n;
    switch (which) {
        case 0: src = Q;  dst = g_in[0]; n = MROWS * DMODEL; break;
        case 1: src = K;  dst = g_in[1]; n = MROWS * DMODEL; break;
        case 2: src = V;  dst = g_in[2]; n = MROWS * DMODEL; break;
        case 3: src = Wq; dst = g_w[0];  n = DMODEL * DMODEL; break;
        case 4: src = Wk; dst = g_w[1];  n = DMODEL * DMODEL; break;
        case 5: src = Wv; dst = g_w[2];  n = DMODEL * DMODEL; break;
        default: src = Wo; dst = g_w[3]; n = DMODEL * DMODEL; break;
    }
    const int stride = gridDim.x * blockDim.x * 4;
    for (int i = (blockIdx.x * blockDim.x + threadIdx.x) * 4; i < n; i += stride) {
        float4 v = *(const float4*)(src + i);
        *(__half2*)(dst + i)     = __floats2half2_rn(v.x, v.y);
        *(__half2*)(dst + i + 2) = __floats2half2_rn(v.z, v.w);
    }
}

// ---------------------------------------------------------------------------
// fp16 GEMM: D[4096,1024] = A @ W^T + bias.
// CTA 128x128, BK=32, 8 warps, 4-stage cp.async pipeline (prefetch 3,
// wait_group 2), pitch-40 smem. __launch_bounds__(256, 2) -> 2 CTAs/SM.
// selArg < 0: sel = blockIdx.z (fused QKV); selArg == 3: out-proj, fp32 out.
// ---------------------------------------------------------------------------
#define ASTRIDE 40
#define A_BYTES (128 * ASTRIDE * 2)   // 10240
#define G_STAGE (2 * A_BYTES)         // 20480: A | B
#define G_SMEM  (4 * G_STAGE)         // 81920
#define NKIT    32

__global__ void __launch_bounds__(256, 2) gemm_mma_kernel(
    const float* __restrict__ b0, const float* __restrict__ b1,
    const float* __restrict__ b2, float* __restrict__ outext, int selArg)
{
    extern __shared__ char smem[];
    const uint32_t sbase = smem_u32(smem);
    const int sel = (selArg < 0) ? (int)blockIdx.z : selArg;
    const float* bias = (sel == 1) ? b1 : (sel == 2) ? b2 : b0;
    const int tid = threadIdx.x;
    const int wid = tid >> 5, lane = tid & 31;
    const int wm = (wid & 3) * 32, wn = (wid >> 2) * 64;
    const int bm = blockIdx.y * 128, bn = blockIdx.x * 128;

    const __half* Ah = (sel < 3) ? g_in[sel] : g_ctx;
    const __half* Bh = g_w[sel];

    float c[2][8][4];
#pragma unroll
    for (int i = 0; i < 2; i++)
#pragma unroll
        for (int j = 0; j < 8; j++)
#pragma unroll
            for (int q = 0; q < 4; q++) c[i][j][q] = 0.f;

    auto fill = [&](int kit) {
        const int st = kit & 3, kk = kit * 32;
        const uint32_t ab = sbase + st * G_STAGE;
        const uint32_t bb = ab + A_BYTES;
#pragma unroll
        for (int t = 0; t < 2; t++) {
            const int id = tid + t * 256;
            const int r = id >> 2, cc = (id & 3) * 8;
            const uint32_t so = (r * ASTRIDE + cc) * 2;
            CP16(ab + so, Ah + (size_t)(bm + r) * DMODEL + kk + cc);
            CP16(bb + so, Bh + (size_t)(bn + r) * DMODEL + kk + cc);
        }
    };

    fill(0); CP_COMMIT();
    fill(1); CP_COMMIT();
    fill(2); CP_COMMIT();

    const int lj = lane >> 3, lr = lane & 7;
    const int a_ro = (lj & 1) * 8 + lr, a_co = (lj >> 1) * 8;
    const int b_no = (lj >> 1) * 8 + lr, b_co = (lj & 1) * 8;

    for (int kit = 0; kit < NKIT; kit++) {
        CP_WAIT2();
        __syncthreads();
        if (kit + 3 < NKIT) fill(kit + 3);
        CP_COMMIT();
        const uint32_t ab = sbase + (kit & 3) * G_STAGE;
        const uint32_t bb = ab + A_BYTES;
#pragma unroll
        for (int k16 = 0; k16 < 2; k16++) {
            uint32_t a[2][4];
#pragma unroll
            for (int mt = 0; mt < 2; mt++)
                LDSM4(a[mt][0], a[mt][1], a[mt][2], a[mt][3],
                      ab + ((wm + mt * 16 + a_ro) * ASTRIDE + k16 * 16 + a_co) * 2);
            uint32_t bf[8][2];
#pragma unroll
            for (int np = 0; np < 4; np++) {
                uint32_t r0, r1, r2, r3;
                LDSM4(r0, r1, r2, r3,
                      bb + ((wn + np * 16 + b_no) * ASTRIDE + k16 * 16 + b_co) * 2);
                bf[2 * np][0] = r0; bf[2 * np][1] = r1;
                bf[2 * np + 1][0] = r2; bf[2 * np + 1][1] = r3;
            }
#pragma unroll
            for (int mt = 0; mt < 2; mt++)
#pragma unroll
                for (int nt = 0; nt < 8; nt++)
                    MMAF16(c[mt][nt], a[mt], bf[nt]);
        }
    }

    const float oscale = (sel == 0) ? 0.18033688011112042f : 1.0f;  // log2e/8 folded into Q
    __half* outh = (sel == 0) ? g_qh : (sel == 1) ? g_kh : g_vh;
#pragma unroll
    for (int mt = 0; mt < 2; mt++) {
#pragma unroll
        for (int nt = 0; nt < 8; nt++) {
            const int n0 = bn + wn + nt * 8 + 2 * (lane & 3);
            const float2 bv = *(const float2*)(bias + n0);
#pragma unroll
            for (int half = 0; half < 2; half++) {
                const int m = bm + wm + mt * 16 + (lane >> 2) + half * 8;
                const float rx = c[mt][nt][2 * half]     + bv.x;
                const float ry = c[mt][nt][2 * half + 1] + bv.y;
                if (sel < 3) {
                    const int b = m >> 11, s2 = m & 2047;
                    const int h = n0 >> 6, dh = n0 & 63;
                    __half2 hv = __floats2half2_rn(rx * oscale, ry * oscale);
                    *(__half2*)(outh + ((size_t)(b * NHEADS + h) * SEQ + s2) * HEADDIM + dh) = hv;
                } else {
                    *(float2*)(outext + (size_t)m * DMODEL + n0) = make_float2(rx, ry);
                }
            }
        }
    }
}

// ---------------------------------------------------------------------------
// fp16 tensor-core causal flash attention, 128 q-rows/CTA (8 warps, 256 thr).
// Halves KV traffic + barriers vs the 64-row version. Warp w owns q rows
// [w*16, w*16+16). Fully-masked warp-tiles are skipped (warp-uniform).
// smem halves: Q[128*72] | K/V double-buffered 64*72 each.
// ---------------------------------------------------------------------------
#define SST 72
#define Q_HALVES (128 * SST)                    // 9216
#define KV_HALVES (64 * SST)                    // 4608
#define ATTN_SMEM ((Q_HALVES + 4 * KV_HALVES) * 2)   // 55296 B

__global__ void __launch_bounds__(256, 2) attn_kernel()
{
    extern __shared__ __half smh[];
    const uint32_t sbase = smem_u32(smh);
    const int qtile = (gridDim.x - 1) - blockIdx.x;   // heavy tiles first
    const int bh  = blockIdx.y;
    const int b   = bh >> 4, h = bh & 15;
    const int tid = threadIdx.x;
    const int w   = tid >> 5, lane = tid & 31;
    const int lj = lane >> 3, lr = lane & 7;
    const int a_ro = (lj & 1) * 8 + lr, a_co = (lj >> 1) * 8;
    const int b_no = (lj >> 1) * 8 + lr, b_co = (lj & 1) * 8;
    const int q4 = lane >> 2, q2 = 2 * (lane & 3);

    const int qrow_base = qtile * 128;
    const int nkt = 2 * qtile + 2;
    const size_t kvoff = (size_t)bh * (SEQ * HEADDIM);

    // Q tile: 128 x 64
    {
        const __half* qg = g_qh + kvoff + (size_t)qrow_base * HEADDIM;
#pragma unroll
        for (int it = 0; it < 4; it++) {
            const int id = tid + it * 256, r = id >> 3, ch = id & 7;
            CP16(sbase + (r * SST + ch * 8) * 2, qg + r * 64 + ch * 8);
        }
    }
    auto fillKV = [&](int kt, int st) {
        const __half* kb = g_kh + kvoff + (size_t)kt * 64 * HEADDIM;
        const __half* vb = g_vh + kvoff + (size_t)kt * 64 * HEADDIM;
        const uint32_t kd = sbase + (Q_HALVES + st * 2 * KV_HALVES) * 2;
        const uint32_t vd = kd + KV_HALVES * 2;
#pragma unroll
        for (int it = 0; it < 2; it++) {
            const int id = tid + it * 256, r = id >> 3, ch = id & 7;
            CP16(kd + (r * SST + ch * 8) * 2, kb + r * 64 + ch * 8);
            CP16(vd + (r * SST + ch * 8) * 2, vb + r * 64 + ch * 8);
        }
    };
    fillKV(0, 0);
    CP_COMMIT();

    float O[8][4];
#pragma unroll
    for (int t = 0; t < 8; t++)
#pragma unroll
        for (int i = 0; i < 4; i++) O[t][i] = 0.f;
    float m0 = -1e30f, m1 = -1e30f, l0 = 0.f, l1 = 0.f;

    const int row0g = qrow_base + w * 16 + q4;   // global q rows of this thread
    const int row1g = row0g + 8;
    const int wrow_max = qrow_base + w * 16 + 15;

    for (int kt = 0; kt < nkt; kt++) {
        const int st = kt & 1;
        if (kt + 1 < nkt) fillKV(kt + 1, st ^ 1);
        CP_COMMIT();
        CP_WAIT1();
        __syncthreads();

        if (kt * 64 <= wrow_max) {   // warp has at least one unmasked column
            const uint32_t Kb = sbase + (Q_HALVES + st * 2 * KV_HALVES) * 2;
            const uint32_t Vb = Kb + KV_HALVES * 2;

            float S[8][4];
#pragma unroll
            for (int t = 0; t < 8; t++)
#pragma unroll
                for (int i = 0; i < 4; i++) S[t][i] = 0.f;
#pragma unroll
            for (int kk = 0; kk < 4; kk++) {
                uint32_t a[4];
                LDSM4(a[0], a[1], a[2], a[3],
                      sbase + ((w * 16 + a_ro) * SST + kk * 16 + a_co) * 2);
#pragma unroll
                for (int np = 0; np < 4; np++) {
                    uint32_t r0, r1, r2, r3;
                    LDSM4(r0, r1, r2, r3,
                          Kb + ((np * 16 + b_no) * SST + kk * 16 + b_co) * 2);
                    uint32_t bA[2] = {r0, r1}, bB[2] = {r2, r3};
                    MMAF16(S[2 * np], a, bA);
                    MMAF16(S[2 * np + 1], a, bB);
                }
            }

            if (kt * 64 + 63 > qrow_base + w * 16) {   // partial mask possible
#pragma unroll
                for (int t = 0; t < 8; t++) {
                    const int c0 = kt * 64 + t * 8 + q2;
                    if (c0     > row0g) S[t][0] = -1e30f;
                    if (c0 + 1 > row0g) S[t][1] = -1e30f;
                    if (c0     > row1g) S[t][2] = -1e30f;
                    if (c0 + 1 > row1g) S[t][3] = -1e30f;
                }
            }

            float mx0 = -1e30f, mx1 = -1e30f;
#pragma unroll
            for (int t = 0; t < 8; t++) {
                mx0 = fmaxf(mx0, fmaxf(S[t][0], S[t][1]));
                mx1 = fmaxf(mx1, fmaxf(S[t][2], S[t][3]));
            }
            mx0 = fmaxf(mx0, __shfl_xor_sync(0xffffffffu, mx0, 1));
            mx0 = fmaxf(mx0, __shfl_xor_sync(0xffffffffu, mx0, 2));
            mx1 = fmaxf(mx1, __shfl_xor_sync(0xffffffffu, mx1, 1));
            mx1 = fmaxf(mx1, __shfl_xor_sync(0xffffffffu, mx1, 2));
            const float nm0 = fmaxf(m0, mx0), nm1 = fmaxf(m1, mx1);
            float scl0, scl1;
            EX2(scl0, m0 - nm0);
            EX2(scl1, m1 - nm1);
            m0 = nm0; m1 = nm1;
            float ls0 = 0.f, ls1 = 0.f;
#pragma unroll
            for (int t = 0; t < 8; t++) {
                EX2(S[t][0], S[t][0] - m0); ls0 += S[t][0];
                EX2(S[t][1], S[t][1] - m0); ls0 += S[t][1];
                EX2(S[t][2], S[t][2] - m1); ls1 += S[t][2];
                EX2(S[t][3], S[t][3] - m1); ls1 += S[t][3];
            }
            ls0 += __shfl_xor_sync(0xffffffffu, ls0, 1);
            ls0 += __shfl_xor_sync(0xffffffffu, ls0, 2);
            ls1 += __shfl_xor_sync(0xffffffffu, ls1, 1);
            ls1 += __shfl_xor_sync(0xffffffffu, ls1, 2);
            l0 = l0 * scl0 + ls0;
            l1 = l1 * scl1 + ls1;
#pragma unroll
            for (int t = 0; t < 8; t++) {
                O[t][0] *= scl0; O[t][1] *= scl0;
                O[t][2] *= scl1; O[t][3] *= scl1;
            }

#pragma unroll
            for (int cch = 0; cch < 4; cch++) {
                uint32_t a[4];
                a[0] = f22h(S[2 * cch][0],     S[2 * cch][1]);
                a[1] = f22h(S[2 * cch][2],     S[2 * cch][3]);
                a[2] = f22h(S[2 * cch + 1][0], S[2 * cch + 1][1]);
                a[3] = f22h(S[2 * cch + 1][2], S[2 * cch + 1][3]);
#pragma unroll
                for (int np = 0; np < 4; np++) {
                    uint32_t r0, r1, r2, r3;
                    LDSMT4(r0, r1, r2, r3,
                           Vb + ((cch * 16 + (lj & 1) * 8 + lr) * SST + np * 16 + (lj >> 1) * 8) * 2);
                    uint32_t bA[2] = {r0, r1}, bB[2] = {r2, r3};
                    MMAF16(O[2 * np], a, bA);
                    MMAF16(O[2 * np + 1], a, bB);
                }
            }
        }
        __syncthreads();
    }

    const float inv0 = 1.f / l0, inv1 = 1.f / l1;
#pragma unroll
    for (int t = 0; t < 8; t++) {
        const int dh = t * 8 + q2;
        const size_t base0 = ((size_t)b * SEQ + row0g) * DMODEL + h * HEADDIM + dh;
        const size_t base1 = ((size_t)b * SEQ + row1g) * DMODEL + h * HEADDIM + dh;
        *(__half2*)(g_ctx + base0) = __floats2half2_rn(O[t][0] * inv0, O[t][1] * inv0);
        *(__half2*)(g_ctx + base1) = __floats2half2_rn(O[t][2] * inv1, O[t][3] * inv1);
    }
}

extern "C" void kernel_launch(void* const* d_in, const int* in_sizes, int n_in,
                              void* d_out, int out_size)
{
    (void)in_sizes; (void)n_in; (void)out_size;
    const float* Q  = (const float*)d_in[0];
    const float* K  = (const float*)d_in[1];
    const float* V  = (const float*)d_in[2];
    const float* Wq = (const float*)d_in[5];
    const float* bq = (const float*)d_in[6];
    const float* Wk = (const float*)d_in[7];
    const float* bk = (const float*)d_in[8];
    const float* Wv = (const float*)d_in[9];
    const float* bv = (const float*)d_in[10];
    const float* Wo = (const float*)d_in[11];
    const float* bo = (const float*)d_in[12];
    float* out = (float*)d_out;

    cudaFuncSetAttribute(gemm_mma_kernel, cudaFuncAttributeMaxDynamicSharedMemorySize, G_SMEM);
    cudaFuncSetAttribute(attn_kernel, cudaFuncAttributeMaxDynamicSharedMemorySize, ATTN_SMEM);

    convert_kernel<<<dim3(512, 7), 256>>>(Q, K, V, Wq, Wk, Wv, Wo);

    dim3 gqkv(DMODEL / 128, MROWS / 128, 3);   // fused QKV: 768 CTAs
    gemm_mma_kernel<<<gqkv, 256, G_SMEM>>>(bq, bk, bv, nullptr, -1);
    attn_kernel<<<dim3(SEQ / 128, BH), 256, ATTN_SMEM>>>();
    dim3 gout(DMODEL / 128, MROWS / 128, 1);
    gemm_mma_kernel<<<gout, 256, G_SMEM>>>(bo, bo, bo, out, 3);
}

// round 17
// speedup vs baseline: 1.0716x; 1.0716x over previous
#include <cuda_runtime.h>
#include <cuda_fp16.h>
#include <cstdint>

#define BATCH    2
#define SEQ      2048
#define DMODEL   1024
#define NHEADS   16
#define HEADDIM  64
#define MROWS    (BATCH * SEQ)
#define BH       (BATCH * NHEADS)

__device__ __half g_in[3][MROWS * DMODEL];    // fp16 inputs
__device__ __half g_w[4][DMODEL * DMODEL];    // fp16 weights
__device__ __half g_qh[BH * SEQ * HEADDIM];   // [bh][s][dh], pre-scaled by log2e/8
__device__ __half g_kh[BH * SEQ * HEADDIM];
__device__ __half g_vh[BH * SEQ * HEADDIM];
__device__ __half g_ctx[MROWS * DMODEL];

__device__ __forceinline__ uint32_t smem_u32(const void* p) {
    uint32_t a;
    asm("{ .reg .u64 t; cvta.to.shared.u64 t, %1; cvt.u32.u64 %0, t; }" : "=r"(a) : "l"(p));
    return a;
}
#define CP16(sp, gp)  asm volatile("cp.async.cg.shared.global [%0], [%1], 16;" :: "r"(sp), "l"(gp))
#define CP_COMMIT()   asm volatile("cp.async.commit_group;" ::: "memory")
#define CP_WAIT1()    asm volatile("cp.async.wait_group 1;" ::: "memory")
#define CP_WAIT2()    asm volatile("cp.async.wait_group 2;" ::: "memory")
#define LDSM4(r0, r1, r2, r3, addr) \
    asm volatile("ldmatrix.sync.aligned.m8n8.x4.shared.b16 {%0,%1,%2,%3}, [%4];" \
                 : "=r"(r0), "=r"(r1), "=r"(r2), "=r"(r3) : "r"(addr))
#define LDSMT4(r0, r1, r2, r3, addr) \
    asm volatile("ldmatrix.sync.aligned.m8n8.x4.trans.shared.b16 {%0,%1,%2,%3}, [%4];" \
                 : "=r"(r0), "=r"(r1), "=r"(r2), "=r"(r3) : "r"(addr))
#define MMAF16(c, a, b) \
    asm volatile("mma.sync.aligned.m16n8k16.row.col.f32.f16.f16.f32 " \
                 "{%0,%1,%2,%3}, {%4,%5,%6,%7}, {%8,%9}, {%0,%1,%2,%3};" \
                 : "+f"((c)[0]), "+f"((c)[1]), "+f"((c)[2]), "+f"((c)[3]) \
                 : "r"((a)[0]), "r"((a)[1]), "r"((a)[2]), "r"((a)[3]), \
                   "r"((b)[0]), "r"((b)[1]))
#define EX2(d, x) asm("ex2.approx.f32 %0, %1;" : "=f"(d) : "f"(x))

__device__ __forceinline__ uint32_t f22h(float a, float b) {
    __half2 h = __floats2half2_rn(a, b);
    return *reinterpret_cast<uint32_t*>(&h);
}

// One launch converts all 7 fp32 tensors to fp16. blockIdx.y selects tensor.
__global__ void convert_kernel(const float* __restrict__ Q, const float* __restrict__ K,
                               const float* __restrict__ V, const float* __restrict__ Wq,
                               const float* __restrict__ Wk, const float* __restrict__ Wv,
                               const float* __restrict__ Wo)
{
    const int which = blockIdx.y;
    const float* src;
    __half* dst;
    int n;
    switch (which) {
        case 0: src = Q;  dst = g_in[0]; n = MROWS * DMODEL; break;
        case 1: src = K;  dst = g_in[1]; n = MROWS * DMODEL; break;
        case 2: src = V;  dst = g_in[2]; n = MROWS * DMODEL; break;
        case 3: src = Wq; dst = g_w[0];  n = DMODEL * DMODEL; break;
        case 4: src = Wk; dst = g_w[1];  n = DMODEL * DMODEL; break;
        case 5: src = Wv; dst = g_w[2];  n = DMODEL * DMODEL; break;
        default: src = Wo; dst = g_w[3]; n = DMODEL * DMODEL; break;
    }
    const int stride = gridDim.x * blockDim.x * 4;
    for (int i = (blockIdx.x * blockDim.x + threadIdx.x) * 4; i < n; i += stride) {
        float4 v = *(const float4*)(src + i);
        *(__half2*)(dst + i)     = __floats2half2_rn(v.x, v.y);
        *(__half2*)(dst + i + 2) = __floats2half2_rn(v.z, v.w);
    }
}

// ---------------------------------------------------------------------------
// fp16 GEMM: D[4096,1024] = A @ W^T + bias.
// CTA 128x128, BK=32, 8 warps, 4-stage cp.async pipeline (prefetch 3,
// wait_group 2), pitch-40 smem. __launch_bounds__(256, 2) -> 2 CTAs/SM.
// selArg < 0: sel = blockIdx.z (fused QKV); selArg == 3: out-proj, fp32 out.
// ---------------------------------------------------------------------------
#define ASTRIDE 40
#define A_BYTES (128 * ASTRIDE * 2)   // 10240
#define G_STAGE (2 * A_BYTES)         // 20480: A | B
#define G_SMEM  (4 * G_STAGE)         // 81920
#define NKIT    32

__global__ void __launch_bounds__(256, 2) gemm_mma_kernel(
    const float* __restrict__ b0, const float* __restrict__ b1,
    const float* __restrict__ b2, float* __restrict__ outext, int selArg)
{
    extern __shared__ char smem[];
    const uint32_t sbase = smem_u32(smem);
    const int sel = (selArg < 0) ? (int)blockIdx.z : selArg;
    const float* bias = (sel == 1) ? b1 : (sel == 2) ? b2 : b0;
    const int tid = threadIdx.x;
    const int wid = tid >> 5, lane = tid & 31;
    const int wm = (wid & 3) * 32, wn = (wid >> 2) * 64;
    const int bm = blockIdx.y * 128, bn = blockIdx.x * 128;

    const __half* Ah = (sel < 3) ? g_in[sel] : g_ctx;
    const __half* Bh = g_w[sel];

    float c[2][8][4];
#pragma unroll
    for (int i = 0; i < 2; i++)
#pragma unroll
        for (int j = 0; j < 8; j++)
#pragma unroll
            for (int q = 0; q < 4; q++) c[i][j][q] = 0.f;

    auto fill = [&](int kit) {
        const int st = kit & 3, kk = kit * 32;
        const uint32_t ab = sbase + st * G_STAGE;
        const uint32_t bb = ab + A_BYTES;
#pragma unroll
        for (int t = 0; t < 2; t++) {
            const int id = tid + t * 256;
            const int r = id >> 2, cc = (id & 3) * 8;
            const uint32_t so = (r * ASTRIDE + cc) * 2;
            CP16(ab + so, Ah + (size_t)(bm + r) * DMODEL + kk + cc);
            CP16(bb + so, Bh + (size_t)(bn + r) * DMODEL + kk + cc);
        }
    };

    fill(0); CP_COMMIT();
    fill(1); CP_COMMIT();
    fill(2); CP_COMMIT();

    const int lj = lane >> 3, lr = lane & 7;
    const int a_ro = (lj & 1) * 8 + lr, a_co = (lj >> 1) * 8;
    const int b_no = (lj >> 1) * 8 + lr, b_co = (lj & 1) * 8;

    for (int kit = 0; kit < NKIT; kit++) {
        CP_WAIT2();
        __syncthreads();
        if (kit + 3 < NKIT) fill(kit + 3);
        CP_COMMIT();
        const uint32_t ab = sbase + (kit & 3) * G_STAGE;
        const uint32_t bb = ab + A_BYTES;
#pragma unroll
        for (int k16 = 0; k16 < 2; k16++) {
            uint32_t a[2][4];
#pragma unroll
            for (int mt = 0; mt < 2; mt++)
                LDSM4(a[mt][0], a[mt][1], a[mt][2], a[mt][3],
                      ab + ((wm + mt * 16 + a_ro) * ASTRIDE + k16 * 16 + a_co) * 2);
            uint32_t bf[8][2];
#pragma unroll
            for (int np = 0; np < 4; np++) {
                uint32_t r0, r1, r2, r3;
                LDSM4(r0, r1, r2, r3,
                      bb + ((wn + np * 16 + b_no) * ASTRIDE + k16 * 16 + b_co) * 2);
                bf[2 * np][0] = r0; bf[2 * np][1] = r1;
                bf[2 * np + 1][0] = r2; bf[2 * np + 1][1] = r3;
            }
#pragma unroll
            for (int mt = 0; mt < 2; mt++)
#pragma unroll
                for (int nt = 0; nt < 8; nt++)
                    MMAF16(c[mt][nt], a[mt], bf[nt]);
        }
    }

    const float oscale = (sel == 0) ? 0.18033688011112042f : 1.0f;  // log2e/8 folded into Q
    __half* outh = (sel == 0) ? g_qh : (sel == 1) ? g_kh : g_vh;
#pragma unroll
    for (int mt = 0; mt < 2; mt++) {
#pragma unroll
        for (int nt = 0; nt < 8; nt++) {
            const int n0 = bn + wn + nt * 8 + 2 * (lane & 3);
            const float2 bv = *(const float2*)(bias + n0);
#pragma unroll
            for (int half = 0; half < 2; half++) {
                const int m = bm + wm + mt * 16 + (lane >> 2) + half * 8;
                const float rx = c[mt][nt][2 * half]     + bv.x;
                const float ry = c[mt][nt][2 * half + 1] + bv.y;
                if (sel < 3) {
                    const int b = m >> 11, s2 = m & 2047;
                    const int h = n0 >> 6, dh = n0 & 63;
                    __half2 hv = __floats2half2_rn(rx * oscale, ry * oscale);
                    *(__half2*)(outh + ((size_t)(b * NHEADS + h) * SEQ + s2) * HEADDIM + dh) = hv;
                } else {
                    *(float2*)(outext + (size_t)m * DMODEL + n0) = make_float2(rx, ry);
                }
            }
        }
    }
}

// ---------------------------------------------------------------------------
// fp16 tensor-core causal flash attention — round-13 winner (64 q-rows,
// 4 warps, all warps do identical work per K-tile; balanced barriers).
// ---------------------------------------------------------------------------
#define SST 72
#define ATTN_SMEM (5 * 64 * SST * 2)   // 46080 B

__global__ void __launch_bounds__(128) attn_kernel()
{
    extern __shared__ __half smh[];
    const uint32_t sbase = smem_u32(smh);
    const int qt  = (gridDim.x - 1) - blockIdx.x;   // heavy tiles first
    const int bh  = blockIdx.y;
    const int b   = bh >> 4, h = bh & 15;
    const int tid = threadIdx.x;
    const int w   = tid >> 5, lane = tid & 31;
    const int lj = lane >> 3, lr = lane & 7;
    const int a_ro = (lj & 1) * 8 + lr, a_co = (lj >> 1) * 8;
    const int b_no = (lj >> 1) * 8 + lr, b_co = (lj & 1) * 8;
    const int q4 = lane >> 2, q2 = 2 * (lane & 3);

    const size_t kvoff = (size_t)bh * (SEQ * HEADDIM);
    {
        const __half* qg = g_qh + kvoff + (size_t)qt * 64 * HEADDIM;
#pragma unroll
        for (int it = 0; it < 4; it++) {
            const int id = tid + it * 128, r = id >> 3, ch = id & 7;
            CP16(sbase + (r * SST + ch * 8) * 2, qg + r * 64 + ch * 8);
        }
    }
    auto fillKV = [&](int kt, int st) {
        const __half* kb = g_kh + kvoff + (size_t)kt * 64 * HEADDIM;
        const __half* vb = g_vh + kvoff + (size_t)kt * 64 * HEADDIM;
        const uint32_t kd = sbase + (4608 + st * 9216) * 2;
        const uint32_t vd = sbase + (9216 + st * 9216) * 2;
#pragma unroll
        for (int it = 0; it < 4; it++) {
            const int id = tid + it * 128, r = id >> 3, ch = id & 7;
            CP16(kd + (r * SST + ch * 8) * 2, kb + r * 64 + ch * 8);
            CP16(vd + (r * SST + ch * 8) * 2, vb + r * 64 + ch * 8);
        }
    };
    fillKV(0, 0);
    CP_COMMIT();

    float O[8][4];
#pragma unroll
    for (int t = 0; t < 8; t++)
#pragma unroll
        for (int i = 0; i < 4; i++) O[t][i] = 0.f;
    float m0 = -1e30f, m1 = -1e30f, l0 = 0.f, l1 = 0.f;

    for (int kt = 0; kt <= qt; kt++) {
        const int st = kt & 1;
        if (kt < qt) fillKV(kt + 1, st ^ 1);
        CP_COMMIT();
        CP_WAIT1();
        __syncthreads();
        const uint32_t Kb = sbase + (4608 + st * 9216) * 2;
        const uint32_t Vb = sbase + (9216 + st * 9216) * 2;

        float S[8][4];
#pragma unroll
        for (int t = 0; t < 8; t++)
#pragma unroll
            for (int i = 0; i < 4; i++) S[t][i] = 0.f;
#pragma unroll
        for (int kk = 0; kk < 4; kk++) {
            uint32_t a[4];
            LDSM4(a[0], a[1], a[2], a[3],
                  sbase + ((w * 16 + a_ro) * SST + kk * 16 + a_co) * 2);
#pragma unroll
            for (int np = 0; np < 4; np++) {
                uint32_t r0, r1, r2, r3;
                LDSM4(r0, r1, r2, r3,
                      Kb + ((np * 16 + b_no) * SST + kk * 16 + b_co) * 2);
                uint32_t bA[2] = {r0, r1}, bB[2] = {r2, r3};
                MMAF16(S[2 * np], a, bA);
                MMAF16(S[2 * np + 1], a, bB);
            }
        }

        if (kt == qt) {
            const int row0 = w * 16 + q4, row1 = row0 + 8;
#pragma unroll
            for (int t = 0; t < 8; t++) {
                const int c0 = t * 8 + q2;
                if (c0     > row0) S[t][0] = -1e30f;
                if (c0 + 1 > row0) S[t][1] = -1e30f;
                if (c0     > row1) S[t][2] = -1e30f;
                if (c0 + 1 > row1) S[t][3] = -1e30f;
            }
        }

        float mx0 = -1e30f, mx1 = -1e30f;
#pragma unroll
        for (int t = 0; t < 8; t++) {
            mx0 = fmaxf(mx0, fmaxf(S[t][0], S[t][1]));
            mx1 = fmaxf(mx1, fmaxf(S[t][2], S[t][3]));
        }
        mx0 = fmaxf(mx0, __shfl_xor_sync(0xffffffffu, mx0, 1));
        mx0 = fmaxf(mx0, __shfl_xor_sync(0xffffffffu, mx0, 2));
        mx1 = fmaxf(mx1, __shfl_xor_sync(0xffffffffu, mx1, 1));
        mx1 = fmaxf(mx1, __shfl_xor_sync(0xffffffffu, mx1, 2));
        const float nm0 = fmaxf(m0, mx0), nm1 = fmaxf(m1, mx1);
        float scl0, scl1;
        EX2(scl0, m0 - nm0);
        EX2(scl1, m1 - nm1);
        m0 = nm0; m1 = nm1;
        float ls0 = 0.f, ls1 = 0.f;
#pragma unroll
        for (int t = 0; t < 8; t++) {
            EX2(S[t][0], S[t][0] - m0); ls0 += S[t][0];
            EX2(S[t][1], S[t][1] - m0); ls0 += S[t][1];
            EX2(S[t][2], S[t][2] - m1); ls1 += S[t][2];
            EX2(S[t][3], S[t][3] - m1); ls1 += S[t][3];
        }
        ls0 += __shfl_xor_sync(0xffffffffu, ls0, 1);
        ls0 += __shfl_xor_sync(0xffffffffu, ls0, 2);
        ls1 += __shfl_xor_sync(0xffffffffu, ls1, 1);
        ls1 += __shfl_xor_sync(0xffffffffu, ls1, 2);
        l0 = l0 * scl0 + ls0;
        l1 = l1 * scl1 + ls1;
#pragma unroll
        for (int t = 0; t < 8; t++) {
            O[t][0] *= scl0; O[t][1] *= scl0;
            O[t][2] *= scl1; O[t][3] *= scl1;
        }

#pragma unroll
        for (int cch = 0; cch < 4; cch++) {
            uint32_t a[4];
            a[0] = f22h(S[2 * cch][0],     S[2 * cch][1]);
            a[1] = f22h(S[2 * cch][2],     S[2 * cch][3]);
            a[2] = f22h(S[2 * cch + 1][0], S[2 * cch + 1][1]);
            a[3] = f22h(S[2 * cch + 1][2], S[2 * cch + 1][3]);
#pragma unroll
            for (int np = 0; np < 4; np++) {
                uint32_t r0, r1, r2, r3;
                LDSMT4(r0, r1, r2, r3,
                       Vb + ((cch * 16 + (lj & 1) * 8 + lr) * SST + np * 16 + (lj >> 1) * 8) * 2);
                uint32_t bA[2] = {r0, r1}, bB[2] = {r2, r3};
                MMAF16(O[2 * np], a, bA);
                MMAF16(O[2 * np + 1], a, bB);
            }
        }
        __syncthreads();
    }

    const float inv0 = 1.f / l0, inv1 = 1.f / l1;
    const int r0g = qt * 64 + w * 16 + q4, r1g = r0g + 8;
#pragma unroll
    for (int t = 0; t < 8; t++) {
        const int dh = t * 8 + q2;
        const size_t base0 = ((size_t)b * SEQ + r0g) * DMODEL + h * HEADDIM + dh;
        const size_t base1 = ((size_t)b * SEQ + r1g) * DMODEL + h * HEADDIM + dh;
        *(__half2*)(g_ctx + base0) = __floats2half2_rn(O[t][0] * inv0, O[t][1] * inv0);
        *(__half2*)(g_ctx + base1) = __floats2half2_rn(O[t][2] * inv1, O[t][3] * inv1);
    }
}

extern "C" void kernel_launch(void* const* d_in, const int* in_sizes, int n_in,
                              void* d_out, int out_size)
{
    (void)in_sizes; (void)n_in; (void)out_size;
    const float* Q  = (const float*)d_in[0];
    const float* K  = (const float*)d_in[1];
    const float* V  = (const float*)d_in[2];
    const float* Wq = (const float*)d_in[5];
    const float* bq = (const float*)d_in[6];
    const float* Wk = (const float*)d_in[7];
    const float* bk = (const float*)d_in[8];
    const float* Wv = (const float*)d_in[9];
    const float* bv = (const float*)d_in[10];
    const float* Wo = (const float*)d_in[11];
    const float* bo = (const float*)d_in[12];
    float* out = (float*)d_out;

    cudaFuncSetAttribute(gemm_mma_kernel, cudaFuncAttributeMaxDynamicSharedMemorySize, G_SMEM);
    cudaFuncSetAttribute(attn_kernel, cudaFuncAttributeMaxDynamicSharedMemorySize, ATTN_SMEM);

    convert_kernel<<<dim3(512, 7), 256>>>(Q, K, V, Wq, Wk, Wv, Wo);

    dim3 gqkv(DMODEL / 128, MROWS / 128, 3);   // fused QKV: 768 CTAs
    gemm_mma_kernel<<<gqkv, 256, G_SMEM>>>(bq, bk, bv, nullptr, -1);
    attn_kernel<<<dim3(SEQ / 64, BH), 128, ATTN_SMEM>>>();
    dim3 gout(DMODEL / 128, MROWS / 128, 1);
    gemm_mma_kernel<<<gout, 256, G_SMEM>>>(bo, bo, bo, out, 3);
}